// round 1
// baseline (speedup 1.0000x reference)
#include <cuda_runtime.h>
#include <cstdint>

#define DD 64
#define NMAX 100000
#define NRELMAX 256

// Static scratch (allocation-free rule): node tables + denominators + exp(E_gate)
__device__ float g_combined[(size_t)NMAX * 2 * DD];  // per node: 64 x {GE, MG} interleaved (512B/node)
__device__ float g_denom[(size_t)NMAX * DD];
__device__ float g_eg2[NRELMAX * DD];

// ---------------------------------------------------------------------------
// K0: zero denom + out (out is poisoned by harness)
// ---------------------------------------------------------------------------
__global__ void k_zero(float* __restrict__ out, int n16) {
    int i = blockIdx.x * blockDim.x + threadIdx.x;
    if (i < n16) {
        float4 z = make_float4(0.f, 0.f, 0.f, 0.f);
        reinterpret_cast<float4*>(g_denom)[i] = z;
        reinterpret_cast<float4*>(out)[i] = z;
    }
}

// ---------------------------------------------------------------------------
// K1b: EG2 = exp(E_gate)  (tiny: n_rel*64 elements)
// ---------------------------------------------------------------------------
__global__ void k_eg2(const float* __restrict__ Eg, int total) {
    int i = blockIdx.x * blockDim.x + threadIdx.x;
    if (i < total) g_eg2[i] = __expf(Eg[i]);
}

// ---------------------------------------------------------------------------
// K1: per-node tables.
//   M  = relu(x @ Vp + Bm)
//   GE = exp(x @ Vg + Bgp)
//   store interleaved {GE[d], MG[d]=M[d]*GE[d]} -> g_combined[node*128 ...]
// Layout: 256 threads, 64 nodes/block; 4 threads per node, 16 dims each.
// V matrices cached in smem; x held in registers, broadcast via shfl.
// ---------------------------------------------------------------------------
__global__ void __launch_bounds__(256) k_tables(
    const float* __restrict__ X, const float* __restrict__ Vp,
    const float* __restrict__ Vg, const float* __restrict__ Bm,
    const float* __restrict__ Bg, int n)
{
    __shared__ float sVp[DD * DD];
    __shared__ float sVg[DD * DD];
    int tid = threadIdx.x;
    {
        const float4* a = reinterpret_cast<const float4*>(Vp);
        const float4* b = reinterpret_cast<const float4*>(Vg);
        float4* sa = reinterpret_cast<float4*>(sVp);
        float4* sb = reinterpret_cast<float4*>(sVg);
        for (int i = tid; i < DD * DD / 4; i += 256) { sa[i] = a[i]; sb[i] = b[i]; }
    }
    __syncthreads();

    int nodeSub = tid >> 2;        // 0..63
    int qd = tid & 3;              // 0..3
    int dbase = qd * 16;
    int gn = blockIdx.x * 64 + nodeSub;

    float xreg[16];
    if (gn < n) {
        const float4* xr = reinterpret_cast<const float4*>(X + (size_t)gn * DD) + qd * 4;
#pragma unroll
        for (int j = 0; j < 4; j++) {
            float4 v = __ldg(xr + j);
            xreg[4 * j + 0] = v.x; xreg[4 * j + 1] = v.y;
            xreg[4 * j + 2] = v.z; xreg[4 * j + 3] = v.w;
        }
    } else {
#pragma unroll
        for (int j = 0; j < 16; j++) xreg[j] = 0.f;
    }

    float accP[16], accG[16];
#pragma unroll
    for (int j = 0; j < 16; j++) { accP[j] = 0.f; accG[j] = 0.f; }

    int laneBase = (tid & 31) & ~3;   // first lane of this node's quad within the warp
#pragma unroll
    for (int k = 0; k < 64; k++) {
        float xk = __shfl_sync(0xffffffffu, xreg[k & 15], laneBase + (k >> 4), 32);
        const float4* vp = reinterpret_cast<const float4*>(sVp + k * DD + dbase);
        const float4* vg = reinterpret_cast<const float4*>(sVg + k * DD + dbase);
#pragma unroll
        for (int q = 0; q < 4; q++) {
            float4 p = vp[q], g = vg[q];
            accP[4 * q + 0] = fmaf(xk, p.x, accP[4 * q + 0]);
            accP[4 * q + 1] = fmaf(xk, p.y, accP[4 * q + 1]);
            accP[4 * q + 2] = fmaf(xk, p.z, accP[4 * q + 2]);
            accP[4 * q + 3] = fmaf(xk, p.w, accP[4 * q + 3]);
            accG[4 * q + 0] = fmaf(xk, g.x, accG[4 * q + 0]);
            accG[4 * q + 1] = fmaf(xk, g.y, accG[4 * q + 1]);
            accG[4 * q + 2] = fmaf(xk, g.z, accG[4 * q + 2]);
            accG[4 * q + 3] = fmaf(xk, g.w, accG[4 * q + 3]);
        }
    }

    if (gn < n) {
        float o[32];
#pragma unroll
        for (int j = 0; j < 16; j++) {
            int d = dbase + j;
            float m  = fmaxf(accP[j] + __ldg(Bm + d), 0.f);
            float ge = __expf(accG[j] + __ldg(Bg + d));
            o[2 * j]     = ge;
            o[2 * j + 1] = m * ge;
        }
        float4* dst = reinterpret_cast<float4*>(g_combined + (size_t)gn * 128 + dbase * 2);
#pragma unroll
        for (int j = 0; j < 8; j++) dst[j] = reinterpret_cast<float4*>(o)[j];
    }
}

// ---------------------------------------------------------------------------
// K2: edge pass. 16 threads/edge, 4 dims/thread.
//   denom[r][d] += GE[s][d]*EG2[t][d]
//   out  [r][d] += MG[s][d]*EG2[t][d]
// via vectorized global reductions (red.global.add.v4.f32).
// ---------------------------------------------------------------------------
__device__ __forceinline__ void red_add_v4(float* p, float a, float b, float c, float d) {
    asm volatile("red.global.add.v4.f32 [%0], {%1,%2,%3,%4};"
                 :: "l"(p), "f"(a), "f"(b), "f"(c), "f"(d) : "memory");
}

__global__ void __launch_bounds__(256) k_edges(
    const int* __restrict__ sidx, const int* __restrict__ ridx,
    const int* __restrict__ tidx, float* __restrict__ out, int E)
{
    int w = blockIdx.x * blockDim.x + threadIdx.x;
    int e = w >> 4;
    if (e >= E) return;
    int lane = w & 15;

    int s = __ldg(sidx + e);
    int r = __ldg(ridx + e);
    int t = __ldg(tidx + e);

    const float4* cb = reinterpret_cast<const float4*>(g_combined + (size_t)s * 128) + lane * 2;
    float4 a = __ldg(cb);      // {GE0, MG0, GE1, MG1}
    float4 b = __ldg(cb + 1);  // {GE2, MG2, GE3, MG3}
    float4 eg = __ldg(reinterpret_cast<const float4*>(g_eg2 + t * DD) + lane);

    float* dden = g_denom + (size_t)r * DD + lane * 4;
    float* dout = out     + (size_t)r * DD + lane * 4;

    red_add_v4(dden, a.x * eg.x, a.z * eg.y, b.x * eg.z, b.z * eg.w);
    red_add_v4(dout, a.y * eg.x, a.w * eg.y, b.y * eg.z, b.w * eg.w);
}

// ---------------------------------------------------------------------------
// K3: out = denom > 0 ? out/denom : 0
// ---------------------------------------------------------------------------
__global__ void k_div(float* __restrict__ out, int n16) {
    int i = blockIdx.x * blockDim.x + threadIdx.x;
    if (i < n16) {
        float4 v = reinterpret_cast<float4*>(out)[i];
        float4 d = reinterpret_cast<const float4*>(g_denom)[i];
        v.x = d.x > 0.f ? v.x / d.x : 0.f;
        v.y = d.y > 0.f ? v.y / d.y : 0.f;
        v.z = d.z > 0.f ? v.z / d.z : 0.f;
        v.w = d.w > 0.f ? v.w / d.w : 0.f;
        reinterpret_cast<float4*>(out)[i] = v;
    }
}

// ---------------------------------------------------------------------------
extern "C" void kernel_launch(void* const* d_in, const int* in_sizes, int n_in,
                              void* d_out, int out_size)
{
    const float* X   = (const float*)d_in[0];  // node_codes [N,64]
    const float* Vp  = (const float*)d_in[1];  // V_proj_sender [64,64]
    const float* Vg  = (const float*)d_in[2];  // V_gate_sender [64,64]
    const float* Eg  = (const float*)d_in[3];  // E_gate [NREL,64]
    const float* Bm  = (const float*)d_in[4];  // B_message [64]
    const float* Bg  = (const float*)d_in[5];  // B_gate_pre [64]
    const int* sidx  = (const int*)d_in[6];    // sender_idx [E]
    const int* ridx  = (const int*)d_in[7];    // receiver_idx [E]
    const int* tidx  = (const int*)d_in[8];    // type_idx [E]
    float* out = (float*)d_out;

    int n        = in_sizes[0] / DD;
    int E        = in_sizes[6];
    int relTotal = in_sizes[3];
    int n16      = n * 16;

    k_zero<<<(n16 + 255) / 256, 256>>>(out, n16);
    k_eg2<<<(relTotal + 255) / 256, 256>>>(Eg, relTotal);
    k_tables<<<(n + 63) / 64, 256>>>(X, Vp, Vg, Bm, Bg, n);

    long long work = (long long)E * 16;
    k_edges<<<(int)((work + 255) / 256), 256>>>(sidx, ridx, tidx, out, E);

    k_div<<<(n16 + 255) / 256, 256>>>(out, n16);
}

// round 2
// speedup vs baseline: 1.6611x; 1.6611x over previous
#include <cuda_runtime.h>
#include <cstdint>

#define DD 64
#define NMAX 100000
#define NRELMAX 256
#define BN 128   // nodes per block in k_tables

// Static scratch: node tables + denominators + exp(E_gate)
__device__ float g_combined[(size_t)NMAX * 2 * DD];  // per node: 64 x {GE, MG} interleaved (512B/node)
__device__ float g_denom[(size_t)NMAX * DD];
__device__ float g_eg2[NRELMAX * DD];

// ---------------------------------------------------------------------------
// K1b: EG2 = exp(E_gate)
// ---------------------------------------------------------------------------
__global__ void k_eg2(const float* __restrict__ Eg, int total) {
    int i = blockIdx.x * blockDim.x + threadIdx.x;
    if (i < total) g_eg2[i] = __expf(Eg[i]);
}

// ---------------------------------------------------------------------------
// K1: per-node tables, register-tiled.
//   M  = relu(x @ Vp + Bm);  GE = exp(x @ Vg + Bgp)
//   store interleaved {GE[d], MG[d]=M[d]*GE[d]} -> g_combined[node*128 ...]
//   also zeroes g_denom and out rows (replaces k_zero).
// Block: 256 threads, BN=128 nodes. Thread = (dim-group dg 0..15 => 4 dims,
// node-group ng 0..15 => 8 nodes). 64 accumulators/thread.
// x tile in smem [node][64]; V rows via __ldg (L1-resident 32KB).
// ---------------------------------------------------------------------------
__global__ void __launch_bounds__(256, 2) k_tables(
    const float* __restrict__ X, const float* __restrict__ Vp,
    const float* __restrict__ Vg, const float* __restrict__ Bm,
    const float* __restrict__ Bg, float* __restrict__ out, int n)
{
    __shared__ float sX[BN][DD];   // 32 KB
    int tid = threadIdx.x;
    int nodeBase = blockIdx.x * BN;

    // stage x tile (coalesced float4 copy; zero-pad past n)
    {
        float4* s4 = reinterpret_cast<float4*>(&sX[0][0]);
        const float4* g4 = reinterpret_cast<const float4*>(X);
        for (int i = tid; i < BN * (DD / 4); i += 256) {
            int node = i >> 4;
            float4 v = make_float4(0.f, 0.f, 0.f, 0.f);
            if (nodeBase + node < n) v = __ldg(g4 + (size_t)(nodeBase + node) * (DD / 4) + (i & 15));
            s4[i] = v;
        }
    }
    __syncthreads();

    int dg = tid & 15;   // dim group: dims 4*dg .. 4*dg+3
    int ng = tid >> 4;   // node group: nodes 8*ng .. 8*ng+7
    int d0 = dg * 4;
    int n0 = ng * 8;

    float accP[8][4], accG[8][4];
#pragma unroll
    for (int i = 0; i < 8; i++)
#pragma unroll
        for (int j = 0; j < 4; j++) { accP[i][j] = 0.f; accG[i][j] = 0.f; }

#pragma unroll 8
    for (int k = 0; k < DD; k++) {
        float4 p = __ldg(reinterpret_cast<const float4*>(Vp + k * DD + d0));
        float4 g = __ldg(reinterpret_cast<const float4*>(Vg + k * DD + d0));
        float xs[8];
#pragma unroll
        for (int i = 0; i < 8; i++) xs[i] = sX[n0 + i][k];
#pragma unroll
        for (int i = 0; i < 8; i++) {
            float x = xs[i];
            accP[i][0] = fmaf(x, p.x, accP[i][0]);
            accP[i][1] = fmaf(x, p.y, accP[i][1]);
            accP[i][2] = fmaf(x, p.z, accP[i][2]);
            accP[i][3] = fmaf(x, p.w, accP[i][3]);
            accG[i][0] = fmaf(x, g.x, accG[i][0]);
            accG[i][1] = fmaf(x, g.y, accG[i][1]);
            accG[i][2] = fmaf(x, g.z, accG[i][2]);
            accG[i][3] = fmaf(x, g.w, accG[i][3]);
        }
    }

    float4 bm = __ldg(reinterpret_cast<const float4*>(Bm + d0));
    float4 bg = __ldg(reinterpret_cast<const float4*>(Bg + d0));
    float4 z4 = make_float4(0.f, 0.f, 0.f, 0.f);

#pragma unroll
    for (int i = 0; i < 8; i++) {
        int gnode = nodeBase + n0 + i;
        if (gnode >= n) break;
        float m0 = fmaxf(accP[i][0] + bm.x, 0.f);
        float m1 = fmaxf(accP[i][1] + bm.y, 0.f);
        float m2 = fmaxf(accP[i][2] + bm.z, 0.f);
        float m3 = fmaxf(accP[i][3] + bm.w, 0.f);
        float e0 = __expf(accG[i][0] + bg.x);
        float e1 = __expf(accG[i][1] + bg.y);
        float e2 = __expf(accG[i][2] + bg.z);
        float e3 = __expf(accG[i][3] + bg.w);
        float4* dst = reinterpret_cast<float4*>(g_combined + (size_t)gnode * 128 + d0 * 2);
        dst[0] = make_float4(e0, m0 * e0, e1, m1 * e1);
        dst[1] = make_float4(e2, m2 * e2, e3, m3 * e3);
        // zero accumulation buffers for k_edges
        *reinterpret_cast<float4*>(g_denom + (size_t)gnode * DD + d0) = z4;
        *reinterpret_cast<float4*>(out + (size_t)gnode * DD + d0) = z4;
    }
}

// ---------------------------------------------------------------------------
// K2: edge pass, 16 threads/edge, 2 edges per thread for MLP.
//   denom[r][d] += GE[s][d]*EG2[t][d]
//   out  [r][d] += MG[s][d]*EG2[t][d]
// ---------------------------------------------------------------------------
__device__ __forceinline__ void red_add_v4(float* p, float a, float b, float c, float d) {
    asm volatile("red.global.add.v4.f32 [%0], {%1,%2,%3,%4};"
                 :: "l"(p), "f"(a), "f"(b), "f"(c), "f"(d) : "memory");
}

__global__ void __launch_bounds__(256) k_edges(
    const int* __restrict__ sidx, const int* __restrict__ ridx,
    const int* __restrict__ tidx, float* __restrict__ out, int E, int half)
{
    int w = blockIdx.x * blockDim.x + threadIdx.x;
    int e0 = w >> 4;
    if (e0 >= half) return;
    int lane = w & 15;
    int e1 = e0 + half;
    bool has1 = (e1 < E);

    int s0 = __ldg(sidx + e0), r0 = __ldg(ridx + e0), t0 = __ldg(tidx + e0);
    int s1 = 0, r1 = 0, t1 = 0;
    if (has1) { s1 = __ldg(sidx + e1); r1 = __ldg(ridx + e1); t1 = __ldg(tidx + e1); }

    const float4* cb0 = reinterpret_cast<const float4*>(g_combined + (size_t)s0 * 128) + lane * 2;
    const float4* cb1 = reinterpret_cast<const float4*>(g_combined + (size_t)s1 * 128) + lane * 2;

    float4 a0 = __ldg(cb0);
    float4 b0 = __ldg(cb0 + 1);
    float4 g0 = __ldg(reinterpret_cast<const float4*>(g_eg2 + t0 * DD) + lane);
    float4 a1, b1, g1;
    if (has1) {
        a1 = __ldg(cb1);
        b1 = __ldg(cb1 + 1);
        g1 = __ldg(reinterpret_cast<const float4*>(g_eg2 + t1 * DD) + lane);
    }

    {
        float* dden = g_denom + (size_t)r0 * DD + lane * 4;
        float* dout = out     + (size_t)r0 * DD + lane * 4;
        red_add_v4(dden, a0.x * g0.x, a0.z * g0.y, b0.x * g0.z, b0.z * g0.w);
        red_add_v4(dout, a0.y * g0.x, a0.w * g0.y, b0.y * g0.z, b0.w * g0.w);
    }
    if (has1) {
        float* dden = g_denom + (size_t)r1 * DD + lane * 4;
        float* dout = out     + (size_t)r1 * DD + lane * 4;
        red_add_v4(dden, a1.x * g1.x, a1.z * g1.y, b1.x * g1.z, b1.z * g1.w);
        red_add_v4(dout, a1.y * g1.x, a1.w * g1.y, b1.y * g1.z, b1.w * g1.w);
    }
}

// ---------------------------------------------------------------------------
// K3: out = denom > 0 ? out/denom : 0
// ---------------------------------------------------------------------------
__global__ void k_div(float* __restrict__ out, int n16) {
    int i = blockIdx.x * blockDim.x + threadIdx.x;
    if (i < n16) {
        float4 v = reinterpret_cast<float4*>(out)[i];
        float4 d = reinterpret_cast<const float4*>(g_denom)[i];
        v.x = d.x > 0.f ? v.x / d.x : 0.f;
        v.y = d.y > 0.f ? v.y / d.y : 0.f;
        v.z = d.z > 0.f ? v.z / d.z : 0.f;
        v.w = d.w > 0.f ? v.w / d.w : 0.f;
        reinterpret_cast<float4*>(out)[i] = v;
    }
}

// ---------------------------------------------------------------------------
extern "C" void kernel_launch(void* const* d_in, const int* in_sizes, int n_in,
                              void* d_out, int out_size)
{
    const float* X   = (const float*)d_in[0];
    const float* Vp  = (const float*)d_in[1];
    const float* Vg  = (const float*)d_in[2];
    const float* Eg  = (const float*)d_in[3];
    const float* Bm  = (const float*)d_in[4];
    const float* Bg  = (const float*)d_in[5];
    const int* sidx  = (const int*)d_in[6];
    const int* ridx  = (const int*)d_in[7];
    const int* tidx  = (const int*)d_in[8];
    float* out = (float*)d_out;

    int n        = in_sizes[0] / DD;
    int E        = in_sizes[6];
    int relTotal = in_sizes[3];
    int n16      = n * 16;

    k_eg2<<<(relTotal + 255) / 256, 256>>>(Eg, relTotal);
    k_tables<<<(n + BN - 1) / BN, 256>>>(X, Vp, Vg, Bm, Bg, out, n);

    int half = (E + 1) / 2;
    long long work = (long long)half * 16;
    k_edges<<<(int)((work + 255) / 256), 256>>>(sidx, ridx, tidx, out, E, half);

    k_div<<<(n16 + 255) / 256, 256>>>(out, n16);
}

// round 3
// speedup vs baseline: 2.0637x; 1.2423x over previous
#include <cuda_runtime.h>
#include <cstdint>

#define DD 64
#define NMAX 100032
#define NRELMAX 256
#define EMAX 2000000
#define BN 128   // nodes per block in k_tables

// Static scratch
__device__ float g_combined[(size_t)NMAX * 2 * DD];  // per node: 64 x {GE, MG} interleaved (512B/node)
__device__ float g_eg2[NRELMAX * DD];
__device__ int   g_count[NMAX];
__device__ int   g_rowstart[NMAX + 1];
__device__ int   g_cursor[NMAX];
__device__ int   g_bsum[1024];
__device__ unsigned g_csr[EMAX];                      // packed (s<<8)|t

// ---------------------------------------------------------------------------
// zero receiver-degree counters
// ---------------------------------------------------------------------------
__global__ void k_zero_count(int n) {
    int i = blockIdx.x * blockDim.x + threadIdx.x;
    if (i < n) g_count[i] = 0;
}

// ---------------------------------------------------------------------------
// EG2 = exp(E_gate)
// ---------------------------------------------------------------------------
__global__ void k_eg2(const float* __restrict__ Eg, int total) {
    int i = blockIdx.x * blockDim.x + threadIdx.x;
    if (i < total) g_eg2[i] = __expf(Eg[i]);
}

// ---------------------------------------------------------------------------
// per-node tables, register-tiled (R2 design, zeroing removed).
//   M = relu(x@Vp+Bm); GE = exp(x@Vg+Bgp); store {GE[d], MG=M*GE} interleaved.
// ---------------------------------------------------------------------------
__global__ void __launch_bounds__(256, 2) k_tables(
    const float* __restrict__ X, const float* __restrict__ Vp,
    const float* __restrict__ Vg, const float* __restrict__ Bm,
    const float* __restrict__ Bg, int n)
{
    __shared__ float sX[BN][DD];   // 32 KB
    int tid = threadIdx.x;
    int nodeBase = blockIdx.x * BN;

    {
        float4* s4 = reinterpret_cast<float4*>(&sX[0][0]);
        const float4* g4 = reinterpret_cast<const float4*>(X);
        for (int i = tid; i < BN * (DD / 4); i += 256) {
            int node = i >> 4;
            float4 v = make_float4(0.f, 0.f, 0.f, 0.f);
            if (nodeBase + node < n) v = __ldg(g4 + (size_t)(nodeBase + node) * (DD / 4) + (i & 15));
            s4[i] = v;
        }
    }
    __syncthreads();

    int dg = tid & 15, ng = tid >> 4;
    int d0 = dg * 4, n0 = ng * 8;

    float accP[8][4], accG[8][4];
#pragma unroll
    for (int i = 0; i < 8; i++)
#pragma unroll
        for (int j = 0; j < 4; j++) { accP[i][j] = 0.f; accG[i][j] = 0.f; }

#pragma unroll 8
    for (int k = 0; k < DD; k++) {
        float4 p = __ldg(reinterpret_cast<const float4*>(Vp + k * DD + d0));
        float4 g = __ldg(reinterpret_cast<const float4*>(Vg + k * DD + d0));
        float xs[8];
#pragma unroll
        for (int i = 0; i < 8; i++) xs[i] = sX[n0 + i][k];
#pragma unroll
        for (int i = 0; i < 8; i++) {
            float x = xs[i];
            accP[i][0] = fmaf(x, p.x, accP[i][0]);
            accP[i][1] = fmaf(x, p.y, accP[i][1]);
            accP[i][2] = fmaf(x, p.z, accP[i][2]);
            accP[i][3] = fmaf(x, p.w, accP[i][3]);
            accG[i][0] = fmaf(x, g.x, accG[i][0]);
            accG[i][1] = fmaf(x, g.y, accG[i][1]);
            accG[i][2] = fmaf(x, g.z, accG[i][2]);
            accG[i][3] = fmaf(x, g.w, accG[i][3]);
        }
    }

    float4 bm = __ldg(reinterpret_cast<const float4*>(Bm + d0));
    float4 bg = __ldg(reinterpret_cast<const float4*>(Bg + d0));

#pragma unroll
    for (int i = 0; i < 8; i++) {
        int gnode = nodeBase + n0 + i;
        if (gnode >= n) break;
        float m0 = fmaxf(accP[i][0] + bm.x, 0.f);
        float m1 = fmaxf(accP[i][1] + bm.y, 0.f);
        float m2 = fmaxf(accP[i][2] + bm.z, 0.f);
        float m3 = fmaxf(accP[i][3] + bm.w, 0.f);
        float e0 = __expf(accG[i][0] + bg.x);
        float e1 = __expf(accG[i][1] + bg.y);
        float e2 = __expf(accG[i][2] + bg.z);
        float e3 = __expf(accG[i][3] + bg.w);
        float4* dst = reinterpret_cast<float4*>(g_combined + (size_t)gnode * 128 + d0 * 2);
        dst[0] = make_float4(e0, m0 * e0, e1, m1 * e1);
        dst[1] = make_float4(e2, m2 * e2, e3, m3 * e3);
    }
}

// ---------------------------------------------------------------------------
// CSR build: histogram -> scan (3 kernels) -> scatter
// ---------------------------------------------------------------------------
__global__ void k_hist(const int* __restrict__ ridx, int E) {
    int i = blockIdx.x * blockDim.x + threadIdx.x;
    if (i < E) atomicAdd(&g_count[__ldg(ridx + i)], 1);
}

__global__ void __launch_bounds__(1024) k_scan1(int n) {
    __shared__ int sd[1024];
    int tid = threadIdx.x;
    int i = blockIdx.x * 1024 + tid;
    sd[tid] = (i < n) ? g_count[i] : 0;
    __syncthreads();
#pragma unroll
    for (int s = 512; s > 0; s >>= 1) {
        if (tid < s) sd[tid] += sd[tid + s];
        __syncthreads();
    }
    if (tid == 0) g_bsum[blockIdx.x] = sd[0];
}

__global__ void __launch_bounds__(1024) k_scan2(int nb, int n) {
    __shared__ int sd[1024];
    int tid = threadIdx.x;
    int v = (tid < nb) ? g_bsum[tid] : 0;
    sd[tid] = v;
    __syncthreads();
#pragma unroll
    for (int d = 1; d < 1024; d <<= 1) {
        int t = (tid >= d) ? sd[tid - d] : 0;
        __syncthreads();
        sd[tid] += t;
        __syncthreads();
    }
    if (tid < nb) g_bsum[tid] = sd[tid] - v;   // exclusive
    if (tid == 1023) g_rowstart[n] = sd[1023]; // total
}

__global__ void __launch_bounds__(1024) k_scan3(int n) {
    __shared__ int sd[1024];
    int tid = threadIdx.x;
    int i = blockIdx.x * 1024 + tid;
    int v = (i < n) ? g_count[i] : 0;
    sd[tid] = v;
    __syncthreads();
#pragma unroll
    for (int d = 1; d < 1024; d <<= 1) {
        int t = (tid >= d) ? sd[tid - d] : 0;
        __syncthreads();
        sd[tid] += t;
        __syncthreads();
    }
    if (i < n) {
        int excl = sd[tid] - v + g_bsum[blockIdx.x];
        g_rowstart[i] = excl;
        g_cursor[i] = excl;
    }
}

__global__ void k_scatter(const int* __restrict__ sidx, const int* __restrict__ ridx,
                          const int* __restrict__ tidx, int E) {
    int i = blockIdx.x * blockDim.x + threadIdx.x;
    if (i < E) {
        int r = __ldg(ridx + i);
        int pos = atomicAdd(&g_cursor[r], 1);
        g_csr[pos] = ((unsigned)__ldg(sidx + i) << 8) | (unsigned)__ldg(tidx + i);
    }
}

// ---------------------------------------------------------------------------
// Accumulate: one 16-lane group per receiver; registers for num/den; write
// out = den>0 ? num/den : 0 directly. No atomics, no k_div.
// ---------------------------------------------------------------------------
__global__ void __launch_bounds__(256) k_accum(float* __restrict__ out, int n) {
    int gid = (blockIdx.x * 256 + threadIdx.x) >> 4;   // receiver
    if (gid >= n) return;                               // group-uniform
    int lane = threadIdx.x & 15;
    int gbase = (threadIdx.x & 31) & ~15;
    unsigned mask = 0xFFFFu << gbase;

    int beg = __ldg(&g_rowstart[gid]);
    int end = __ldg(&g_rowstart[gid + 1]);

    float4 num = make_float4(0.f, 0.f, 0.f, 0.f);
    float4 den = make_float4(0.f, 0.f, 0.f, 0.f);

    for (int chunk = beg; chunk < end; chunk += 16) {
        int m = end - chunk; if (m > 16) m = 16;
        unsigned pk = 0;
        if (chunk + lane < end) pk = __ldg(&g_csr[chunk + lane]);
        for (int j = 0; j < m; j++) {
            unsigned p = __shfl_sync(mask, pk, gbase + j);
            int s = p >> 8;
            int t = p & 255;
            const float4* cb = reinterpret_cast<const float4*>(g_combined + (size_t)s * 128) + lane * 2;
            float4 a = __ldg(cb);       // {GE0,MG0,GE1,MG1}
            float4 b = __ldg(cb + 1);   // {GE2,MG2,GE3,MG3}
            float4 g = __ldg(reinterpret_cast<const float4*>(g_eg2 + t * DD) + lane);
            den.x = fmaf(a.x, g.x, den.x);  num.x = fmaf(a.y, g.x, num.x);
            den.y = fmaf(a.z, g.y, den.y);  num.y = fmaf(a.w, g.y, num.y);
            den.z = fmaf(b.x, g.z, den.z);  num.z = fmaf(b.y, g.z, num.z);
            den.w = fmaf(b.z, g.w, den.w);  num.w = fmaf(b.w, g.w, num.w);
        }
    }

    float4 o;
    o.x = den.x > 0.f ? num.x / den.x : 0.f;
    o.y = den.y > 0.f ? num.y / den.y : 0.f;
    o.z = den.z > 0.f ? num.z / den.z : 0.f;
    o.w = den.w > 0.f ? num.w / den.w : 0.f;
    *(reinterpret_cast<float4*>(out + (size_t)gid * DD) + lane) = o;
}

// ---------------------------------------------------------------------------
extern "C" void kernel_launch(void* const* d_in, const int* in_sizes, int n_in,
                              void* d_out, int out_size)
{
    const float* X   = (const float*)d_in[0];
    const float* Vp  = (const float*)d_in[1];
    const float* Vg  = (const float*)d_in[2];
    const float* Eg  = (const float*)d_in[3];
    const float* Bm  = (const float*)d_in[4];
    const float* Bg  = (const float*)d_in[5];
    const int* sidx  = (const int*)d_in[6];
    const int* ridx  = (const int*)d_in[7];
    const int* tidx  = (const int*)d_in[8];
    float* out = (float*)d_out;

    int n        = in_sizes[0] / DD;
    int E        = in_sizes[6];
    int relTotal = in_sizes[3];
    int nb       = (n + 1023) / 1024;

    k_zero_count<<<(n + 255) / 256, 256>>>(n);
    k_eg2<<<(relTotal + 255) / 256, 256>>>(Eg, relTotal);
    k_tables<<<(n + BN - 1) / BN, 256>>>(X, Vp, Vg, Bm, Bg, n);

    k_hist<<<(E + 255) / 256, 256>>>(ridx, E);
    k_scan1<<<nb, 1024>>>(n);
    k_scan2<<<1, 1024>>>(nb, n);
    k_scan3<<<nb, 1024>>>(n);
    k_scatter<<<(E + 255) / 256, 256>>>(sidx, ridx, tidx, E);

    long long work = (long long)n * 16;
    k_accum<<<(int)((work + 255) / 256), 256>>>(out, n);
}

// round 6
// speedup vs baseline: 2.4512x; 1.1878x over previous
#include <cuda_runtime.h>
#include <cuda_fp16.h>
#include <cstdint>

#define DD 64
#define NMAX 100032
#define NRELMAX 256
#define EMAX 2000000
#define BN 128   // nodes per block in k_tables

// bit-cast helpers (no direct intrinsics exist for half2<->uint)
__device__ __forceinline__ unsigned h2_as_u32(__half2 h) {
    union { __half2 h; unsigned u; } c; c.h = h; return c.u;
}
__device__ __forceinline__ __half2 u32_as_h2(unsigned u) {
    union { unsigned u; __half2 h; } c; c.u = u; return c.h;
}

// Static scratch
// per node: 64 dims x half2{GE, M} = 256 B = 16 uint4
__device__ uint4 g_comb[(size_t)NMAX * 16];
__device__ float g_eg2[NRELMAX * DD];
__device__ int   g_count[NMAX];
__device__ int   g_rowstart[NMAX + 1];
__device__ int   g_cursor[NMAX];
__device__ int   g_bsum[1024];
__device__ unsigned g_csr[EMAX];                      // packed (s<<8)|t

// ---------------------------------------------------------------------------
// init: zero degree counters + EG2 = exp(E_gate)   (merged launch)
// ---------------------------------------------------------------------------
__global__ void k_init(const float* __restrict__ Eg, int n, int relTotal) {
    int i = blockIdx.x * blockDim.x + threadIdx.x;
    if (i < n) g_count[i] = 0;
    if (i < relTotal) g_eg2[i] = __expf(Eg[i]);
}

// ---------------------------------------------------------------------------
// per-node tables, register-tiled.
//   M = relu(x@Vp+Bm); GE = exp(x@Vg+Bgp); store half2{GE, M} per dim.
// ---------------------------------------------------------------------------
__global__ void __launch_bounds__(256, 2) k_tables(
    const float* __restrict__ X, const float* __restrict__ Vp,
    const float* __restrict__ Vg, const float* __restrict__ Bm,
    const float* __restrict__ Bg, int n)
{
    __shared__ float sX[BN][DD];   // 32 KB
    int tid = threadIdx.x;
    int nodeBase = blockIdx.x * BN;

    {
        float4* s4 = reinterpret_cast<float4*>(&sX[0][0]);
        const float4* g4 = reinterpret_cast<const float4*>(X);
        for (int i = tid; i < BN * (DD / 4); i += 256) {
            int node = i >> 4;
            float4 v = make_float4(0.f, 0.f, 0.f, 0.f);
            if (nodeBase + node < n) v = __ldg(g4 + (size_t)(nodeBase + node) * (DD / 4) + (i & 15));
            s4[i] = v;
        }
    }
    __syncthreads();

    int dg = tid & 15, ng = tid >> 4;
    int d0 = dg * 4, n0 = ng * 8;

    float accP[8][4], accG[8][4];
#pragma unroll
    for (int i = 0; i < 8; i++)
#pragma unroll
        for (int j = 0; j < 4; j++) { accP[i][j] = 0.f; accG[i][j] = 0.f; }

#pragma unroll 8
    for (int k = 0; k < DD; k++) {
        float4 p = __ldg(reinterpret_cast<const float4*>(Vp + k * DD + d0));
        float4 g = __ldg(reinterpret_cast<const float4*>(Vg + k * DD + d0));
        float xs[8];
#pragma unroll
        for (int i = 0; i < 8; i++) xs[i] = sX[n0 + i][k];
#pragma unroll
        for (int i = 0; i < 8; i++) {
            float x = xs[i];
            accP[i][0] = fmaf(x, p.x, accP[i][0]);
            accP[i][1] = fmaf(x, p.y, accP[i][1]);
            accP[i][2] = fmaf(x, p.z, accP[i][2]);
            accP[i][3] = fmaf(x, p.w, accP[i][3]);
            accG[i][0] = fmaf(x, g.x, accG[i][0]);
            accG[i][1] = fmaf(x, g.y, accG[i][1]);
            accG[i][2] = fmaf(x, g.z, accG[i][2]);
            accG[i][3] = fmaf(x, g.w, accG[i][3]);
        }
    }

    float4 bm = __ldg(reinterpret_cast<const float4*>(Bm + d0));
    float4 bg = __ldg(reinterpret_cast<const float4*>(Bg + d0));

#pragma unroll
    for (int i = 0; i < 8; i++) {
        int gnode = nodeBase + n0 + i;
        if (gnode >= n) break;
        float m0 = fmaxf(accP[i][0] + bm.x, 0.f);
        float m1 = fmaxf(accP[i][1] + bm.y, 0.f);
        float m2 = fmaxf(accP[i][2] + bm.z, 0.f);
        float m3 = fmaxf(accP[i][3] + bm.w, 0.f);
        float e0 = __expf(accG[i][0] + bg.x);
        float e1 = __expf(accG[i][1] + bg.y);
        float e2 = __expf(accG[i][2] + bg.z);
        float e3 = __expf(accG[i][3] + bg.w);
        uint4 v;
        v.x = h2_as_u32(__floats2half2_rn(e0, m0));   // low=GE, high=M
        v.y = h2_as_u32(__floats2half2_rn(e1, m1));
        v.z = h2_as_u32(__floats2half2_rn(e2, m2));
        v.w = h2_as_u32(__floats2half2_rn(e3, m3));
        g_comb[(size_t)gnode * 16 + dg] = v;
    }
}

// ---------------------------------------------------------------------------
// CSR build: histogram -> scan (3 kernels) -> scatter
// ---------------------------------------------------------------------------
__global__ void k_hist(const int* __restrict__ ridx, int E) {
    int i = blockIdx.x * blockDim.x + threadIdx.x;
    if (i < E) atomicAdd(&g_count[__ldg(ridx + i)], 1);
}

__global__ void __launch_bounds__(1024) k_scan1(int n) {
    __shared__ int sd[1024];
    int tid = threadIdx.x;
    int i = blockIdx.x * 1024 + tid;
    sd[tid] = (i < n) ? g_count[i] : 0;
    __syncthreads();
#pragma unroll
    for (int s = 512; s > 0; s >>= 1) {
        if (tid < s) sd[tid] += sd[tid + s];
        __syncthreads();
    }
    if (tid == 0) g_bsum[blockIdx.x] = sd[0];
}

__global__ void __launch_bounds__(1024) k_scan2(int nb, int n) {
    __shared__ int sd[1024];
    int tid = threadIdx.x;
    int v = (tid < nb) ? g_bsum[tid] : 0;
    sd[tid] = v;
    __syncthreads();
#pragma unroll
    for (int d = 1; d < 1024; d <<= 1) {
        int t = (tid >= d) ? sd[tid - d] : 0;
        __syncthreads();
        sd[tid] += t;
        __syncthreads();
    }
    if (tid < nb) g_bsum[tid] = sd[tid] - v;   // exclusive
    if (tid == 1023) g_rowstart[n] = sd[1023]; // total
}

__global__ void __launch_bounds__(1024) k_scan3(int n) {
    __shared__ int sd[1024];
    int tid = threadIdx.x;
    int i = blockIdx.x * 1024 + tid;
    int v = (i < n) ? g_count[i] : 0;
    sd[tid] = v;
    __syncthreads();
#pragma unroll
    for (int d = 1; d < 1024; d <<= 1) {
        int t = (tid >= d) ? sd[tid - d] : 0;
        __syncthreads();
        sd[tid] += t;
        __syncthreads();
    }
    if (i < n) {
        int excl = sd[tid] - v + g_bsum[blockIdx.x];
        g_rowstart[i] = excl;
        g_cursor[i] = excl;
    }
}

__global__ void k_scatter(const int* __restrict__ sidx, const int* __restrict__ ridx,
                          const int* __restrict__ tidx, int E) {
    int i = blockIdx.x * blockDim.x + threadIdx.x;
    if (i < E) {
        int r = __ldg(ridx + i);
        int pos = atomicAdd(&g_cursor[r], 1);
        g_csr[pos] = ((unsigned)__ldg(sidx + i) << 8) | (unsigned)__ldg(tidx + i);
    }
}

// ---------------------------------------------------------------------------
// Accumulate: one 16-lane group per receiver. fp16 gather (16 B/lane/edge),
// fp32 accumulation. t = GE*eg; den += t; num += M*t  (GE rounding cancels
// in num/den for dominant edges). Writes out directly; no atomics, no k_div.
// ---------------------------------------------------------------------------
__global__ void __launch_bounds__(256) k_accum(float* __restrict__ out, int n) {
    int gid = (blockIdx.x * 256 + threadIdx.x) >> 4;   // receiver
    if (gid >= n) return;                               // group-uniform
    int lane = threadIdx.x & 15;
    int gbase = (threadIdx.x & 31) & ~15;
    unsigned mask = 0xFFFFu << gbase;

    int beg = __ldg(&g_rowstart[gid]);
    int end = __ldg(&g_rowstart[gid + 1]);

    float4 num = make_float4(0.f, 0.f, 0.f, 0.f);
    float4 den = make_float4(0.f, 0.f, 0.f, 0.f);

    for (int chunk = beg; chunk < end; chunk += 16) {
        int m = end - chunk; if (m > 16) m = 16;
        unsigned pk = 0;
        if (chunk + lane < end) pk = __ldg(&g_csr[chunk + lane]);
        for (int j = 0; j < m; j++) {
            unsigned p = __shfl_sync(mask, pk, gbase + j);
            int s = p >> 8;
            int t = p & 255;
            uint4 raw = __ldg(&g_comb[(size_t)s * 16 + lane]);
            float4 g = __ldg(reinterpret_cast<const float4*>(g_eg2 + t * DD) + lane);
            float2 f0 = __half22float2(u32_as_h2(raw.x));  // {GE0, M0}
            float2 f1 = __half22float2(u32_as_h2(raw.y));
            float2 f2 = __half22float2(u32_as_h2(raw.z));
            float2 f3 = __half22float2(u32_as_h2(raw.w));
            float t0 = f0.x * g.x;  den.x += t0;  num.x = fmaf(f0.y, t0, num.x);
            float t1 = f1.x * g.y;  den.y += t1;  num.y = fmaf(f1.y, t1, num.y);
            float t2 = f2.x * g.z;  den.z += t2;  num.z = fmaf(f2.y, t2, num.z);
            float t3 = f3.x * g.w;  den.w += t3;  num.w = fmaf(f3.y, t3, num.w);
        }
    }

    float4 o;
    o.x = den.x > 0.f ? num.x / den.x : 0.f;
    o.y = den.y > 0.f ? num.y / den.y : 0.f;
    o.z = den.z > 0.f ? num.z / den.z : 0.f;
    o.w = den.w > 0.f ? num.w / den.w : 0.f;
    *(reinterpret_cast<float4*>(out + (size_t)gid * DD) + lane) = o;
}

// ---------------------------------------------------------------------------
extern "C" void kernel_launch(void* const* d_in, const int* in_sizes, int n_in,
                              void* d_out, int out_size)
{
    const float* X   = (const float*)d_in[0];
    const float* Vp  = (const float*)d_in[1];
    const float* Vg  = (const float*)d_in[2];
    const float* Eg  = (const float*)d_in[3];
    const float* Bm  = (const float*)d_in[4];
    const float* Bg  = (const float*)d_in[5];
    const int* sidx  = (const int*)d_in[6];
    const int* ridx  = (const int*)d_in[7];
    const int* tidx  = (const int*)d_in[8];
    float* out = (float*)d_out;

    int n        = in_sizes[0] / DD;
    int E        = in_sizes[6];
    int relTotal = in_sizes[3];
    int nb       = (n + 1023) / 1024;

    k_init<<<(n + 255) / 256, 256>>>(Eg, n, relTotal);
    k_tables<<<(n + BN - 1) / BN, 256>>>(X, Vp, Vg, Bm, Bg, n);

    k_hist<<<(E + 255) / 256, 256>>>(ridx, E);
    k_scan1<<<nb, 1024>>>(n);
    k_scan2<<<1, 1024>>>(nb, n);
    k_scan3<<<nb, 1024>>>(n);
    k_scatter<<<(E + 255) / 256, 256>>>(sidx, ridx, tidx, E);

    long long work = (long long)n * 16;
    k_accum<<<(int)((work + 255) / 256), 256>>>(out, n);
}